// round 1
// baseline (speedup 1.0000x reference)
#include <cuda_runtime.h>
#include <math.h>

// Scratch (allocation-free: __device__ globals)
__device__ float g_y[8 * 1152];     // pooled means, (b, c*9+k) order
__device__ float g_gate[8 * 1152];  // gate, flat (b, g*128+c) order == broadcast channel order

// ---------------------------------------------------------------------------
// Kernel 1: per-(b,c) plane reduction -> y[b, c*9+k]
// mean(conv(x_c, w_{c,k})) = (1/HW) * sum_tap w[tap] * S[tap] + bf
// S[tap] = plane sum minus excluded boundary row/col (+corner add-back)
// ---------------------------------------------------------------------------
__global__ __launch_bounds__(256) void se_reduce_kernel(
    const float* __restrict__ x, const float* __restrict__ wf,
    const float* __restrict__ bf)
{
    const int bc = blockIdx.x;          // 0..1023
    const int b  = bc >> 7;
    const int c  = bc & 127;
    const float* xp = x + ((size_t)bc << 12);   // 64*64 plane
    const int t = threadIdx.x;

    float T = 0.f, top = 0.f, bot = 0.f, lef = 0.f, rig = 0.f;
    for (int i = t; i < 4096; i += 256) {
        float v = xp[i];
        int r = i >> 6, w = i & 63;
        T += v;
        if (r == 0)  top += v;
        if (r == 63) bot += v;
        if (w == 0)  lef += v;
        if (w == 63) rig += v;
    }
    // warp reduce 5 quantities
    #pragma unroll
    for (int off = 16; off; off >>= 1) {
        T   += __shfl_down_sync(0xffffffffu, T,   off);
        top += __shfl_down_sync(0xffffffffu, top, off);
        bot += __shfl_down_sync(0xffffffffu, bot, off);
        lef += __shfl_down_sync(0xffffffffu, lef, off);
        rig += __shfl_down_sync(0xffffffffu, rig, off);
    }
    __shared__ float sred[5][8];
    const int wid = t >> 5, lid = t & 31;
    if (lid == 0) {
        sred[0][wid] = T; sred[1][wid] = top; sred[2][wid] = bot;
        sred[3][wid] = lef; sred[4][wid] = rig;
    }
    __syncthreads();
    __shared__ float S[9];
    if (t == 0) {
        float Tt = 0.f, tp = 0.f, bt = 0.f, lf = 0.f, rg = 0.f;
        #pragma unroll
        for (int i = 0; i < 8; i++) {
            Tt += sred[0][i]; tp += sred[1][i]; bt += sred[2][i];
            lf += sred[3][i]; rg += sred[4][i];
        }
        const float c00 = xp[0], c0w = xp[63];
        const float ch0 = xp[63 * 64], chw = xp[63 * 64 + 63];
        #pragma unroll
        for (int dy = 0; dy < 3; dy++) {
            #pragma unroll
            for (int dx = 0; dx < 3; dx++) {
                int sy = dy - 1, sx = dx - 1;
                float s = Tt;
                if (sy == -1) s -= bt; else if (sy == 1) s -= tp;
                if (sx == -1) s -= rg; else if (sx == 1) s -= lf;
                if (sy == -1 && sx == -1) s += chw;
                if (sy == -1 && sx ==  1) s += ch0;
                if (sy ==  1 && sx == -1) s += c0w;
                if (sy ==  1 && sx ==  1) s += c00;
                S[dy * 3 + dx] = s;
            }
        }
    }
    __syncthreads();
    if (t < 9) {
        const int k = t;
        const float* wp = wf + (size_t)(c * 9 + k) * 9;
        float acc = 0.f;
        #pragma unroll
        for (int tap = 0; tap < 9; tap++) acc = fmaf(wp[tap], S[tap], acc);
        g_y[b * 1152 + c * 9 + k] = acc * (1.f / 4096.f) + bf[c * 9 + k];
    }
}

// ---------------------------------------------------------------------------
// Kernel 2: gating MLPs. One block per batch, 128 threads (one per channel c).
// gate[b, g*128+c] = sigmoid(fc_c)[b,c,g] * sigmoid(fc_k)[b,g,c]
// ---------------------------------------------------------------------------
__device__ __forceinline__ float sigmoidf_(float v) {
    return 1.f / (1.f + __expf(-v));
}

__global__ __launch_bounds__(128) void se_gate_kernel(
    const float* __restrict__ wc1, const float* __restrict__ wc2,
    const float* __restrict__ wk1, const float* __restrict__ wk2)
{
    const int b = blockIdx.x;   // 0..7
    const int c = threadIdx.x;  // 0..127
    __shared__ float sy[128][9];
    __shared__ float shk[9][8];

    float yr[9];
    #pragma unroll
    for (int n = 0; n < 9; n++) {
        yr[n] = g_y[b * 1152 + c * 9 + n];
        sy[c][n] = yr[n];
    }
    // fc_c: hc[o] = relu(sum_n y[n] * wc1[c,o,n]);  ac[n] = sigmoid(sum_o hc[o]*wc2[c,n,o])
    float hc[3];
    #pragma unroll
    for (int o = 0; o < 3; o++) {
        float s = 0.f;
        #pragma unroll
        for (int n = 0; n < 9; n++)
            s = fmaf(yr[n], wc1[(c * 3 + o) * 9 + n], s);
        hc[o] = fmaxf(s, 0.f);
    }
    float ac[9];
    #pragma unroll
    for (int n = 0; n < 9; n++) {
        float s = 0.f;
        #pragma unroll
        for (int o = 0; o < 3; o++)
            s = fmaf(hc[o], wc2[(c * 9 + n) * 3 + o], s);
        ac[n] = sigmoidf_(s);
    }
    __syncthreads();
    // fc_k: hk[g,o] = relu(sum_c y[c,g] * wk1[g,o,c])
    if (c < 72) {
        const int g = c / 8, o = c % 8;
        float s = 0.f;
        for (int c2 = 0; c2 < 128; c2++)
            s = fmaf(sy[c2][g], wk1[(g * 8 + o) * 128 + c2], s);
        shk[g][o] = fmaxf(s, 0.f);
    }
    __syncthreads();
    // ak[g,c] = sigmoid(sum_o hk[g,o] * wk2[g,c,o]);  gate flat = ac[c,g]*ak[g,c]
    #pragma unroll
    for (int g = 0; g < 9; g++) {
        float s = 0.f;
        #pragma unroll
        for (int o = 0; o < 8; o++)
            s = fmaf(shk[g][o], wk2[(g * 128 + c) * 8 + o], s);
        g_gate[b * 1152 + g * 128 + c] = ac[g] * sigmoidf_(s);
    }
}

// ---------------------------------------------------------------------------
// Kernel 3: recompute depthwise-expand conv, apply gate, write out + attn.
// One block per (b,c). x plane staged in smem with zero halo (66 x stride 68).
// Each thread: 4 positions x (4 horiz pixels) x 9 output channels.
// ---------------------------------------------------------------------------
__global__ __launch_bounds__(256) void se_apply_kernel(
    const float* __restrict__ x, const float* __restrict__ wf,
    const float* __restrict__ bf, float* __restrict__ out,
    size_t attn_off /* in floats; 0 => no attn half */)
{
    const int bc = blockIdx.x;
    const int b  = bc >> 7;
    const int c  = bc & 127;
    const int t  = threadIdx.x;

    __shared__ __align__(16) float sh[66 * 68];
    __shared__ float wsh[9][9];
    __shared__ float bsh[9], gsh[9];

    for (int i = t; i < 66 * 68; i += 256) sh[i] = 0.f;
    if (t < 81) wsh[t / 9][t % 9] = wf[(size_t)c * 81 + t];
    if (t < 9) {
        bsh[t] = bf[c * 9 + t];
        gsh[t] = g_gate[b * 1152 + c * 9 + t];
    }
    __syncthreads();
    const float* xp = x + ((size_t)bc << 12);
    for (int i = t; i < 4096; i += 256) {
        int r = i >> 6, w = i & 63;
        sh[(r + 1) * 68 + (w + 1)] = xp[i];
    }
    __syncthreads();

    const size_t planeF4 = (size_t)(b * 1152 + c * 9) * 1024;  // float4 units
    float4* o1 = (float4*)out;
    float4* o2 = (float4*)(out + attn_off);
    const bool do_attn = (attn_off != 0);

    #pragma unroll
    for (int j = 0; j < 4; j++) {
        const int idx4 = t + (j << 8);         // 0..1023 float4 slots in plane
        const int r  = idx4 >> 4;              // output row
        const int wb = (idx4 & 15) << 2;       // output col base (mult of 4)
        // window: padded rows r..r+2, padded cols wb..wb+5
        float v[3][6];
        #pragma unroll
        for (int dy = 0; dy < 3; dy++) {
            const float* rp = &sh[(r + dy) * 68 + wb];
            float4 a = *(const float4*)rp;
            float2 e = *(const float2*)(rp + 4);
            v[dy][0] = a.x; v[dy][1] = a.y; v[dy][2] = a.z; v[dy][3] = a.w;
            v[dy][4] = e.x; v[dy][5] = e.y;
        }
        #pragma unroll
        for (int k = 0; k < 9; k++) {
            float a0 = 0.f, a1 = 0.f, a2 = 0.f, a3 = 0.f;
            #pragma unroll
            for (int dy = 0; dy < 3; dy++) {
                #pragma unroll
                for (int dx = 0; dx < 3; dx++) {
                    const float wv = wsh[k][dy * 3 + dx];
                    a0 = fmaf(wv, v[dy][dx    ], a0);
                    a1 = fmaf(wv, v[dy][dx + 1], a1);
                    a2 = fmaf(wv, v[dy][dx + 2], a2);
                    a3 = fmaf(wv, v[dy][dx + 3], a3);
                }
            }
            const float g = gsh[k], bb = bsh[k];
            float4 ov;
            ov.x = (a0 + bb) * g; ov.y = (a1 + bb) * g;
            ov.z = (a2 + bb) * g; ov.w = (a3 + bb) * g;
            const size_t pos = planeF4 + (size_t)k * 1024 + idx4;
            o1[pos] = ov;
            if (do_attn) {
                float4 gv; gv.x = g; gv.y = g; gv.z = g; gv.w = g;
                o2[pos] = gv;
            }
        }
    }
}

// ---------------------------------------------------------------------------
extern "C" void kernel_launch(void* const* d_in, const int* in_sizes, int n_in,
                              void* d_out, int out_size) {
    const float* x   = (const float*)d_in[0];
    const float* wf  = (const float*)d_in[1];
    const float* bf  = (const float*)d_in[2];
    const float* wc1 = (const float*)d_in[3];
    const float* wc2 = (const float*)d_in[4];
    const float* wk1 = (const float*)d_in[5];
    const float* wk2 = (const float*)d_in[6];
    float* out = (float*)d_out;

    const size_t N = (size_t)8 * 1152 * 64 * 64;  // 37,748,736
    const size_t attn_off = ((size_t)out_size >= 2 * N) ? N : 0;

    se_reduce_kernel<<<1024, 256>>>(x, wf, bf);
    se_gate_kernel<<<8, 128>>>(wc1, wc2, wk1, wk2);
    se_apply_kernel<<<1024, 256>>>(x, wf, bf, out, attn_off);
}

// round 4
// speedup vs baseline: 1.1448x; 1.1448x over previous
#include <cuda_runtime.h>
#include <math.h>

// Scratch (allocation-free: __device__ globals)
__device__ float g_y[8 * 1152];     // pooled means, (b, c*9+k) order
__device__ float g_gate[8 * 1152];  // gate, FLAT torch order: [b, k*128+c]

// ---------------------------------------------------------------------------
// Kernel 1: per-(b,c) plane reduction -> y[b, c*9+k], float4 loads.
// mean(conv(x_c, w_{c,k})) = (1/HW) * sum_tap w[tap]*S[tap] + bf
// ---------------------------------------------------------------------------
__global__ __launch_bounds__(256) void se_reduce_kernel(
    const float* __restrict__ x, const float* __restrict__ wf,
    const float* __restrict__ bf)
{
    const int bc = blockIdx.x;          // 0..1023
    const int b  = bc >> 7;
    const int c  = bc & 127;
    const float* xp = x + ((size_t)bc << 12);
    const float4* xp4 = (const float4*)xp;
    const int t = threadIdx.x;

    float4 a[4];
    #pragma unroll
    for (int j = 0; j < 4; j++) a[j] = xp4[t + (j << 8)];

    float T = 0.f, top = 0.f, bot = 0.f, lef = 0.f, rig = 0.f;
    #pragma unroll
    for (int j = 0; j < 4; j++) {
        const int q  = t + (j << 8);
        const int r  = q >> 4;
        const int w4 = q & 15;
        const float s = (a[j].x + a[j].y) + (a[j].z + a[j].w);
        T += s;
        if (r == 0)   top += s;
        if (r == 63)  bot += s;
        if (w4 == 0)  lef += a[j].x;
        if (w4 == 15) rig += a[j].w;
    }
    #pragma unroll
    for (int off = 16; off; off >>= 1) {
        T   += __shfl_down_sync(0xffffffffu, T,   off);
        top += __shfl_down_sync(0xffffffffu, top, off);
        bot += __shfl_down_sync(0xffffffffu, bot, off);
        lef += __shfl_down_sync(0xffffffffu, lef, off);
        rig += __shfl_down_sync(0xffffffffu, rig, off);
    }
    __shared__ float sred[5][8];
    const int wid = t >> 5, lid = t & 31;
    if (lid == 0) {
        sred[0][wid] = T; sred[1][wid] = top; sred[2][wid] = bot;
        sred[3][wid] = lef; sred[4][wid] = rig;
    }
    __syncthreads();
    __shared__ float S[9];
    if (t == 0) {
        float Tt = 0.f, tp = 0.f, bt = 0.f, lf = 0.f, rg = 0.f;
        #pragma unroll
        for (int i = 0; i < 8; i++) {
            Tt += sred[0][i]; tp += sred[1][i]; bt += sred[2][i];
            lf += sred[3][i]; rg += sred[4][i];
        }
        const float c00 = xp[0], c0w = xp[63];
        const float ch0 = xp[63 * 64], chw = xp[63 * 64 + 63];
        #pragma unroll
        for (int dy = 0; dy < 3; dy++) {
            #pragma unroll
            for (int dx = 0; dx < 3; dx++) {
                int sy = dy - 1, sx = dx - 1;
                float s = Tt;
                if (sy == -1) s -= bt; else if (sy == 1) s -= tp;
                if (sx == -1) s -= rg; else if (sx == 1) s -= lf;
                if (sy == -1 && sx == -1) s += chw;
                if (sy == -1 && sx ==  1) s += ch0;
                if (sy ==  1 && sx == -1) s += c0w;
                if (sy ==  1 && sx ==  1) s += c00;
                S[dy * 3 + dx] = s;
            }
        }
    }
    __syncthreads();
    if (t < 9) {
        const int k = t;
        const float* wp = wf + (size_t)(c * 9 + k) * 9;
        float acc = 0.f;
        #pragma unroll
        for (int tap = 0; tap < 9; tap++) acc = fmaf(wp[tap], S[tap], acc);
        g_y[b * 1152 + c * 9 + k] = acc * (1.f / 4096.f) + bf[c * 9 + k];
    }
}

// ---------------------------------------------------------------------------
// Kernel 2: gating MLPs. One block per batch, 128 threads (one per channel).
// Writes g_gate in torch flat order: flat = g*128 + c.
// ---------------------------------------------------------------------------
__device__ __forceinline__ float sigmoidf_(float v) {
    return 1.f / (1.f + __expf(-v));
}

__global__ __launch_bounds__(128) void se_gate_kernel(
    const float* __restrict__ wc1, const float* __restrict__ wc2,
    const float* __restrict__ wk1, const float* __restrict__ wk2)
{
    const int b = blockIdx.x;   // 0..7
    const int c = threadIdx.x;  // 0..127
    __shared__ float sy[128][9];
    __shared__ float shk[9][8];

    float yr[9];
    #pragma unroll
    for (int n = 0; n < 9; n++) {
        yr[n] = g_y[b * 1152 + c * 9 + n];
        sy[c][n] = yr[n];
    }
    float hc[3];
    #pragma unroll
    for (int o = 0; o < 3; o++) {
        float s = 0.f;
        #pragma unroll
        for (int n = 0; n < 9; n++)
            s = fmaf(yr[n], wc1[(c * 3 + o) * 9 + n], s);
        hc[o] = fmaxf(s, 0.f);
    }
    float ac[9];
    #pragma unroll
    for (int n = 0; n < 9; n++) {
        float s = 0.f;
        #pragma unroll
        for (int o = 0; o < 3; o++)
            s = fmaf(hc[o], wc2[(c * 9 + n) * 3 + o], s);
        ac[n] = sigmoidf_(s);
    }
    __syncthreads();
    if (c < 72) {
        const int g = c / 8, o = c % 8;
        float s = 0.f;
        for (int c2 = 0; c2 < 128; c2++)
            s = fmaf(sy[c2][g], wk1[(g * 8 + o) * 128 + c2], s);
        shk[g][o] = fmaxf(s, 0.f);
    }
    __syncthreads();
    #pragma unroll
    for (int g = 0; g < 9; g++) {
        float s = 0.f;
        #pragma unroll
        for (int o = 0; o < 8; o++)
            s = fmaf(shk[g][o], wk2[(g * 128 + c) * 8 + o], s);
        g_gate[b * 1152 + g * 128 + c] = ac[g] * sigmoidf_(s);
    }
}

// ---------------------------------------------------------------------------
// Kernel 3: attn constant fill. One block per output plane (9216 blocks).
// attn[b, ch, :, :] = gate_flat[b, ch]  ==  g_gate[blockIdx.x].
// ---------------------------------------------------------------------------
__global__ __launch_bounds__(256) void se_fill_kernel(float* __restrict__ attn)
{
    const int p = blockIdx.x;         // 0..9215 == b*1152 + ch
    const float g = g_gate[p];
    float4 gv; gv.x = g; gv.y = g; gv.z = g; gv.w = g;
    float4* __restrict__ o = (float4*)attn + ((size_t)p << 10);
    const int t = threadIdx.x;
    #pragma unroll
    for (int j = 0; j < 4; j++) o[t + (j << 8)] = gv;
}

// ---------------------------------------------------------------------------
// Kernel 4: recompute conv + gate, write out only. Half-plane per block:
// 2048 blocks, 256 threads. smem: 34 rows x 68 (zero halo), col offset 1.
// Gate for output channel (c*9+k) is g_gate FLAT at index c*9+k.
// ---------------------------------------------------------------------------
__global__ __launch_bounds__(256) void se_apply_kernel(
    const float* __restrict__ x, const float* __restrict__ wf,
    const float* __restrict__ bf, float* __restrict__ out)
{
    const int bh   = blockIdx.x;      // 0..2047
    const int bc   = bh >> 1;
    const int half = bh & 1;
    const int b    = bc >> 7;
    const int c    = bc & 127;
    const int t    = threadIdx.x;
    const int r0   = half << 5;       // 0 or 32

    __shared__ __align__(16) float sh[34 * 68];
    __shared__ float wsh[9][9];
    __shared__ float bsh[9], gsh[9];

    // zero smem (34*68 = 2312 floats = 578 float4)
    float4* sh4 = (float4*)sh;
    for (int i = t; i < 578; i += 256) {
        float4 z; z.x = 0.f; z.y = 0.f; z.z = 0.f; z.w = 0.f;
        sh4[i] = z;
    }
    if (t < 81) wsh[t / 9][t % 9] = wf[(size_t)c * 81 + t];
    if (t < 9) {
        bsh[t] = bf[c * 9 + t];
        gsh[t] = g_gate[b * 1152 + c * 9 + t];   // FLAT index (torch order)
    }
    __syncthreads();

    // load 33 global rows (gstart..gstart+32) into padded rows
    const int gstart = half ? 31 : 0;         // first global row to load
    const float4* xp4 = (const float4*)(x + ((size_t)bc << 12));
    for (int i = t; i < 33 * 16; i += 256) {
        const int lrow = i >> 4;
        const int w4   = i & 15;
        const int grow = gstart + lrow;
        const int prow = grow - (r0 - 1);      // padded row 0..33
        float4 a = xp4[(grow << 4) + w4];
        float* d = &sh[prow * 68 + 1 + (w4 << 2)];
        d[0] = a.x; d[1] = a.y; d[2] = a.z; d[3] = a.w;
    }
    __syncthreads();

    const size_t planeF4 = (size_t)(b * 1152 + c * 9) * 1024 + (r0 << 4);
    float4* o1 = (float4*)out;

    #pragma unroll
    for (int j = 0; j < 2; j++) {
        const int idx4 = t + (j << 8);         // 0..511 slots in half plane
        const int lr   = idx4 >> 4;            // local row 0..31
        const int wb   = (idx4 & 15) << 2;     // col base
        float v[3][6];
        #pragma unroll
        for (int dy = 0; dy < 3; dy++) {
            const float* rp = &sh[(lr + dy) * 68 + wb];
            float4 aa = *(const float4*)rp;
            float2 ee = *(const float2*)(rp + 4);
            v[dy][0] = aa.x; v[dy][1] = aa.y; v[dy][2] = aa.z; v[dy][3] = aa.w;
            v[dy][4] = ee.x; v[dy][5] = ee.y;
        }
        #pragma unroll
        for (int k = 0; k < 9; k++) {
            float a0 = 0.f, a1 = 0.f, a2 = 0.f, a3 = 0.f;
            #pragma unroll
            for (int dy = 0; dy < 3; dy++) {
                #pragma unroll
                for (int dx = 0; dx < 3; dx++) {
                    const float wv = wsh[k][dy * 3 + dx];
                    a0 = fmaf(wv, v[dy][dx    ], a0);
                    a1 = fmaf(wv, v[dy][dx + 1], a1);
                    a2 = fmaf(wv, v[dy][dx + 2], a2);
                    a3 = fmaf(wv, v[dy][dx + 3], a3);
                }
            }
            const float g = gsh[k], bb = bsh[k];
            float4 ov;
            ov.x = (a0 + bb) * g; ov.y = (a1 + bb) * g;
            ov.z = (a2 + bb) * g; ov.w = (a3 + bb) * g;
            o1[planeF4 + (size_t)k * 1024 + idx4] = ov;
        }
    }
}

// ---------------------------------------------------------------------------
extern "C" void kernel_launch(void* const* d_in, const int* in_sizes, int n_in,
                              void* d_out, int out_size) {
    const float* x   = (const float*)d_in[0];
    const float* wf  = (const float*)d_in[1];
    const float* bf  = (const float*)d_in[2];
    const float* wc1 = (const float*)d_in[3];
    const float* wc2 = (const float*)d_in[4];
    const float* wk1 = (const float*)d_in[5];
    const float* wk2 = (const float*)d_in[6];
    float* out = (float*)d_out;

    const size_t N = (size_t)8 * 1152 * 64 * 64;  // 37,748,736
    const bool has_attn = ((size_t)out_size >= 2 * N);

    se_reduce_kernel<<<1024, 256>>>(x, wf, bf);
    se_gate_kernel<<<8, 128>>>(wc1, wc2, wk1, wk2);
    if (has_attn) se_fill_kernel<<<9216, 256>>>(out + N);
    se_apply_kernel<<<2048, 256>>>(x, wf, bf, out);
}